// round 14
// baseline (speedup 1.0000x reference)
#include <cuda_runtime.h>
#include <cuda_fp16.h>
#include <math_constants.h>

#define NFLOWS 8
#define SUBH   72            // fp16 sub-row stride (halves) = 144B, 16B-aligned

// ---------------------------------------------------------------------------
// Device-global precomputed tables (no allocations anywhere — harness rule)
// All divergently-gathered tables are fp16 (continuity of the piecewise-linear
// composite makes threshold rounding harmless; coef fp16 costs ~1e-4 rel).
// ---------------------------------------------------------------------------
__device__ __align__(16) float          g_conv[NFLOWS][12];        // w0..w8, c0..c2
__device__ __align__(16) float          g_piv[NFLOWS][8];          // fp16-rounded pivots (as fp32)
__device__ __align__(16) __half         g_thrh[NFLOWS][SUBH];      // sorted coarse thr fp16 (+pads)
__device__ __align__(16) __half         g_subh[NFLOWS][65 * SUBH]; // sub-breakpoints fp16 (+INF pads)
__device__ __align__(16) unsigned short g_coefh[NFLOWS][4225][8];  // {al0..3, be0..3} fp16
__device__ float g_L[9], g_bm[3], g_totc;

// ---------------------------------------------------------------------------
// Fused prep: grid (65, 8) x 256 threads (R10 structure, fp16 outputs).
// ALL FP32 math (B300 vector fp64 ~2 lane-ops/cyc/SM — R6 regression).
// ---------------------------------------------------------------------------
__global__ __launch_bounds__(256)
void k_prep(const float* __restrict__ L_tril, const float* __restrict__ bm,
            const float* __restrict__ ls, const float* __restrict__ sh,
            const float* __restrict__ P,  const float* __restrict__ ss,
            const float* __restrict__ lm, const float* __restrict__ um,
            const float* __restrict__ lls,
            const float* __restrict__ W1, const float* __restrict__ b1,
            const float* __restrict__ W2, const float* __restrict__ b2,
            const float* __restrict__ W3, const float* __restrict__ b3) {
    __shared__ float  sW2[4096];
    __shared__ float  sa[64], sbv[64], sthr[64], sx[64];
    __shared__ int    srank[64], ssub[64];
    __shared__ float  sP[64], sQ[64];
    __shared__ unsigned char sin_[64], sact0[64];
    __shared__ float  sw3[4][64];
    __shared__ float  sb3v[4];

    const int s = blockIdx.x;   // 0..64
    const int f = blockIdx.y;
    const int t = threadIdx.x;

    for (int i = t; i < 4096; i += 256) sW2[i] = W2[f * 4096 + i];
    if (t < 64) {
        float a = W1[f * 64 + t], b = b1[f * 64 + t];
        sa[t] = a; sbv[t] = b;
        sx[t] = (a != 0.f) ? (-b / a) : CUDART_INF_F;   // raw thresholds (temp)
        sw3[0][t] = W3[f * 256 + t];
        sw3[1][t] = W3[f * 256 + 64 + t];
        sw3[2][t] = W3[f * 256 + 128 + t];
        sw3[3][t] = W3[f * 256 + 192 + t];
    }
    if (t >= 64 && t < 68) sb3v[t - 64] = b3[f * 4 + (t - 64)];
    __syncthreads();

    // per-block redundant rank sort of the 64 layer-1 breakpoints
    if (t < 64) {
        float tk = sx[t];
        int r = 0;
        for (int j = 0; j < 64; ++j) {
            float tj = sx[j];
            r += (tj < tk) || (tj == tk && j < t);
        }
        srank[t] = r;
        sthr[r] = tk;
    }
    __syncthreads();

    // block s==0 of each flow publishes header tables
    if (s == 0) {
        if (t < 64)              g_thrh[f][t] = __float2half_ru(sthr[t]);
        if (t >= 64 && t < SUBH) g_thrh[f][t] = __float2half(CUDART_INF_F);
        if (t >= 72 && t < 80)   // pivots = fp16-rounded thr[8k+7], stored as fp32
            g_piv[f][t - 72] = __half2float(__float2half_ru(sthr[8 * (t - 72) + 7]));
        if (t == 64) {
            float el[3], shv[3];
            for (int d = 0; d < 3; d++) { el[d] = expf(ls[f * 3 + d]); shv[d] = sh[f * 3 + d]; }
            float l[3][3], U[3][3];
            for (int aa = 0; aa < 3; aa++)
                for (int bb = 0; bb < 3; bb++) {
                    l[aa][bb] = (bb < aa ? lm[f * 9 + aa * 3 + bb] : (aa == bb ? 1.f : 0.f));
                    U[aa][bb] = (bb > aa ? um[f * 9 + aa * 3 + bb] : 0.f);
                }
            for (int d = 0; d < 3; d++) U[d][d] = ss[f * 3 + d] * expf(lls[f * 3 + d]);
            float A[3][3], Wm[3][3];
            for (int aa = 0; aa < 3; aa++)
                for (int bb = 0; bb < 3; bb++) {
                    float s2 = 0.f;
                    for (int q = 0; q < 3; q++) s2 += l[aa][q] * U[q][bb];
                    A[aa][bb] = s2;
                }
            for (int aa = 0; aa < 3; aa++)
                for (int bb = 0; bb < 3; bb++) {
                    float s2 = 0.f;
                    for (int q = 0; q < 3; q++) s2 += P[f * 9 + aa * 3 + q] * A[q][bb];
                    Wm[aa][bb] = s2;
                }
            for (int aa = 0; aa < 3; aa++) {
                float cs = 0.f;
                for (int bb = 0; bb < 3; bb++) {
                    float wcv = Wm[aa][bb] * el[bb];
                    g_conv[f][aa * 3 + bb] = wcv;
                    cs += wcv * shv[bb];
                }
                g_conv[f][9 + aa] = cs;
            }
        }
        if (f == 0 && t == 65) {
            float Lt[3][3], cov[3][3];
            for (int aa = 0; aa < 3; aa++)
                for (int bb = 0; bb < 3; bb++)
                    Lt[aa][bb] = (bb <= aa ? L_tril[aa * 3 + bb] : 0.f) + (aa == bb ? 1e-6f : 0.f);
            for (int aa = 0; aa < 3; aa++)
                for (int bb = 0; bb < 3; bb++) {
                    float s2 = 0.f;
                    for (int q = 0; q < 3; q++) s2 += Lt[aa][q] * Lt[bb][q];
                    cov[aa][bb] = s2;
                }
            float L00 = sqrtf(cov[0][0]);
            float L10 = cov[1][0] / L00, L20 = cov[2][0] / L00;
            float L11 = sqrtf(cov[1][1] - L10 * L10);
            float L21 = (cov[2][1] - L20 * L10) / L11;
            float L22 = sqrtf(cov[2][2] - L20 * L20 - L21 * L21);
            float Lm[9] = {L00, 0.f, 0.f, L10, L11, 0.f, L20, L21, L22};
            for (int q = 0; q < 9; q++) g_L[q] = Lm[q];
            for (int q = 0; q < 3; q++) g_bm[q] = bm[q];
        }
        if (f == 0 && t == 66) {
            float tot = 0.f;
            for (int q = 0; q < NFLOWS * 3; q++) tot += ls[q] + lls[q];
            g_totc = tot;
        }
    }

    const float lo = (s == 0)  ? -CUDART_INF_F : sthr[s - 1];
    const float hi = (s == 64) ?  CUDART_INF_F : sthr[s];

    if (t < 64) {
        const int u = t;
        float Pd = 0.f, Qd = b2[f * 64 + u];
        for (int j = 0; j < 64; ++j) {
            float aj = sa[j];
            bool act = (aj > 0.f) ? (srank[j] < s)
                     : (aj < 0.f) ? (srank[j] >= s)
                                  : (sbv[j] > 0.f);
            if (act) {
                float w = sW2[u * 64 + j];
                Pd = fmaf(w, aj, Pd);
                Qd = fmaf(w, sbv[j], Qd);
            }
        }
        sP[u] = Pd; sQ[u] = Qd;
        float xu = (Pd != 0.f) ? (-Qd / Pd) : CUDART_INF_F;
        bool inside = (Pd != 0.f) && (xu > lo) && (xu < hi);
        sx[u]  = inside ? xu : CUDART_INF_F;
        sin_[u] = inside ? 1 : 0;
        bool a0;                                // active just above lo?
        if (Pd > 0.f)      a0 = (xu <= lo);
        else if (Pd < 0.f) a0 = (xu > lo);
        else               a0 = (Qd > 0.f);
        sact0[u] = a0 ? 1 : 0;
    }
    __syncthreads();
    if (t < 64) {
        float key = sx[t];
        int r = 0;
        for (int j = 0; j < 64; ++j) {
            float xj = sx[j];
            r += (xj < key) || (xj == key && j < t);
        }
        ssub[t] = r;
        g_subh[f][s * SUBH + r] = __float2half_ru(key);   // sorted, INF at top
    }
    if (t >= 64 && t < SUBH)                              // pads = +INF
        g_subh[f][s * SUBH + t] = __float2half(CUDART_INF_F);
    __syncthreads();

    // coef build: thread t -> (j = t>>2, r = t&3); j=64 handled by t<4 pass 2
    {
        int j = t >> 2, r = t & 3;
        for (int pass = 0; pass < 2; ++pass) {
            if (pass == 1) { if (t >= 4) break; j = 64; r = t; }
            float al = 0.f, be = sb3v[r];
            const float* w3r = sw3[r];
            for (int u = 0; u < 64; ++u) {
                bool act = (sact0[u] != 0) != ((sin_[u] != 0) && (ssub[u] < j));
                if (act) {
                    float w = w3r[u];
                    al = fmaf(w, sP[u], al);
                    be = fmaf(w, sQ[u], be);
                }
            }
            int idx = s * 65 + j;
            g_coefh[f][idx][r]     = __half_as_ushort(__float2half(al));
            g_coefh[f][idx][4 + r] = __half_as_ushort(__float2half(be));
        }
    }
}

// ---------------------------------------------------------------------------
// Main kernel: 512 thr/CTA, one sample/thread, no smem/barriers.
// Per flow: 3+2 uniform loads, ONE 16B fp16 coarse gather, ONE 16B fp16 fine
// scan load (usually), ONE 16B fp16 coef load. ~45 wf/warp/flow vs ~100 (R11).
// Fine scan is HARD-BOUNDED (9 iterations max) — defensive vs container kills.
// ---------------------------------------------------------------------------
__device__ __forceinline__ int cnt8_lt(uint4 hv, float x) {
    float2 a = __half22float2(*(__half2*)&hv.x);
    float2 b = __half22float2(*(__half2*)&hv.y);
    float2 c = __half22float2(*(__half2*)&hv.z);
    float2 d = __half22float2(*(__half2*)&hv.w);
    return (a.x < x) + (a.y < x) + (b.x < x) + (b.y < x)
         + (c.x < x) + (c.y < x) + (d.x < x) + (d.y < x);
}

__global__ __launch_bounds__(512)
void glow_main(const float* __restrict__ eps, float* __restrict__ out, int N) {
    int gi = blockIdx.x * 512 + threadIdx.x;
    const bool valid = gi < N;
    const int i = valid ? gi : (N - 1);

    const float L0 = g_L[0], L3 = g_L[3], L4 = g_L[4],
                L6 = g_L[6], L7 = g_L[7], L8 = g_L[8];
    const float m0 = g_bm[0], m1 = g_bm[1], m2 = g_bm[2];

    float e0 = eps[3 * i], e1 = eps[3 * i + 1], e2 = eps[3 * i + 2];
    float z0 = m0 + L0 * e0;
    float z1 = m1 + L3 * e0 + L4 * e1;
    float z2 = m2 + L6 * e0 + L7 * e1 + L8 * e2;
    float ld = 0.f;

    #pragma unroll
    for (int f = 0; f < NFLOWS; ++f) {
        // conv constants: 3 uniform float4 loads
        float4 cv0 = __ldg((const float4*)g_conv[f]);        // w0..w3
        float4 cv1 = __ldg((const float4*)g_conv[f] + 1);    // w4..w7
        float4 cv2 = __ldg((const float4*)g_conv[f] + 2);    // w8, c0, c1, c2

        float n0 = cv2.y + cv0.x * z0 + cv0.y * z1 + cv0.z * z2;
        float n1 = cv2.z + cv0.w * z0 + cv1.x * z1 + cv1.y * z2;
        float n2 = cv2.w + cv1.z * z0 + cv1.w * z1 + cv2.x * z2;
        z0 = n0; z1 = n1; z2 = n2;

        // pivots: 2 uniform float4 loads (fp16-rounded values, row-consistent)
        float4 p0 = __ldg((const float4*)g_piv[f]);
        float4 p1 = __ldg((const float4*)g_piv[f] + 1);
        int o = (p0.x < z0) + (p0.y < z0) + (p0.z < z0) + (p0.w < z0)
              + (p1.x < z0) + (p1.y < z0) + (p1.z < z0) + (p1.w < z0);
        int ob = (o > 7 ? 7 : o) * 8;

        // coarse rank: one 16B gather of 8 fp16 thresholds
        uint4 hv = __ldg((const uint4*)(g_thrh[f] + ob));
        int sS = ob + cnt8_lt(hv, z0);

        // fine rank: fp16 linear scan, 8 thresholds per 16B load (avg 1 load).
        // Hard-bounded: jS advances by 8 only while all-below; row is INF-padded
        // at [64,72) so iteration 9 (jS=64) always breaks.
        const __half* rowp = g_subh[f] + sS * SUBH;
        int jS = 0;
        #pragma unroll 1
        for (int it = 0; it < 9; ++it) {
            uint4 rv = __ldg((const uint4*)(rowp + jS));
            int c = cnt8_lt(rv, z0);
            jS += c;
            if (c < 8) break;
        }

        // exact affine MLP output (fp16 coefs, ONE 16B load) + coupling
        uint4 ce = __ldg((const uint4*)g_coefh[f] + (sS * 65 + jS));
        float2 a01 = __half22float2(*(__half2*)&ce.x);
        float2 a23 = __half22float2(*(__half2*)&ce.y);
        float2 b01 = __half22float2(*(__half2*)&ce.z);
        float2 b23 = __half22float2(*(__half2*)&ce.w);

        float o0 = fmaf(a01.x, z0, b01.x), o1 = fmaf(a01.y, z0, b01.y);
        float o2 = fmaf(a23.x, z0, b23.x), o3 = fmaf(a23.y, z0, b23.y);
        z1 = fmaf(z1, __expf(o2), o0);
        z2 = fmaf(z2, __expf(o3), o1);
        ld += o2 + o3;
    }

    if (valid) {
        out[3 * i]     = z0;
        out[3 * i + 1] = __expf(z1);
        out[3 * i + 2] = __expf(z2);
        out[3 * N + i] = ld + g_totc + z1 + z2;
    }
}

// ---------------------------------------------------------------------------
// Launch. Inputs (metadata order): eps, L_tril, base_mean, an_log_scale,
// an_shift, perm_p, sign_s, lu_l, lu_u, lu_log_s, W1, b1, W2, b2, W3, b3
// Output: [z_t (N,3) row-major][log_det (N)] float32 (layout verified R4..R11)
// ---------------------------------------------------------------------------
extern "C" void kernel_launch(void* const* d_in, const int* in_sizes, int n_in,
                              void* d_out, int out_size) {
    const float* eps    = (const float*)d_in[0];
    const float* L_tril = (const float*)d_in[1];
    const float* bm     = (const float*)d_in[2];
    const float* an_ls  = (const float*)d_in[3];
    const float* an_sh  = (const float*)d_in[4];
    const float* perm   = (const float*)d_in[5];
    const float* ss     = (const float*)d_in[6];
    const float* lu_l   = (const float*)d_in[7];
    const float* lu_u   = (const float*)d_in[8];
    const float* lu_ls  = (const float*)d_in[9];
    const float* W1     = (const float*)d_in[10];
    const float* b1     = (const float*)d_in[11];
    const float* W2     = (const float*)d_in[12];
    const float* b2     = (const float*)d_in[13];
    const float* W3     = (const float*)d_in[14];
    const float* b3     = (const float*)d_in[15];
    float* out = (float*)d_out;

    int N = in_sizes[0] / 3;

    k_prep<<<dim3(65, NFLOWS), 256>>>(L_tril, bm, an_ls, an_sh, perm, ss,
                                      lu_l, lu_u, lu_ls, W1, b1, W2, b2, W3, b3);
    glow_main<<<(N + 511) / 512, 512>>>(eps, out, N);
}

// round 16
// speedup vs baseline: 1.7498x; 1.7498x over previous
#include <cuda_runtime.h>
#include <cuda_fp16.h>
#include <math_constants.h>

#define NFLOWS 8

// ---------------------------------------------------------------------------
// Device-global precomputed tables (no allocations anywhere — harness rule)
// Thresholds/search tables fp32 (R14 showed fp16 compares cost more ALU than
// they save in L1 wavefronts). Coef table fp16: halves the dominant random-
// gather sector count at +4 H2F per flow; rel_err ~1.6e-4 validated in R14.
// ---------------------------------------------------------------------------
__device__ float          g_hdr[NFLOWS][80];        // [0:64] sorted coarse thr, [64:73] wc, [73:76] c
__device__ float          g_sub[NFLOWS][4228];      // [s*65 + j] sorted sub-breakpoints (+INF pads)
__device__ __align__(16) unsigned short g_coefh[NFLOWS][4225][8];  // {al0..3, be0..3} fp16
__device__ float          g_L[9], g_bm[3], g_totc;

// ---------------------------------------------------------------------------
// Fused prep: grid (65, 8) x 128 threads (R9 structure — best measured total).
// ALL FP32 math (B300 vector fp64 ~2 lane-ops/cyc/SM — R6 regression).
// ---------------------------------------------------------------------------
__global__ void k_prep(const float* __restrict__ L_tril, const float* __restrict__ bm,
                       const float* __restrict__ ls, const float* __restrict__ sh,
                       const float* __restrict__ P,  const float* __restrict__ ss,
                       const float* __restrict__ lm, const float* __restrict__ um,
                       const float* __restrict__ lls,
                       const float* __restrict__ W1, const float* __restrict__ b1,
                       const float* __restrict__ W2, const float* __restrict__ b2,
                       const float* __restrict__ W3, const float* __restrict__ b3) {
    __shared__ float  sW2[4096];
    __shared__ float  sa[64], sbv[64], sthr[64], sx[64];
    __shared__ int    srank[64], ssub[64];
    __shared__ float  sP[64], sQ[64];
    __shared__ unsigned char sin_[64], sact0[64];
    __shared__ float  sw3[4][64];
    __shared__ float  sb3v[4];

    const int s = blockIdx.x;   // 0..64
    const int f = blockIdx.y;
    const int t = threadIdx.x;

    for (int i = t; i < 4096; i += 128) sW2[i] = W2[f * 4096 + i];
    if (t < 64) {
        float a = W1[f * 64 + t], b = b1[f * 64 + t];
        sa[t] = a; sbv[t] = b;
        sx[t] = (a != 0.f) ? (-b / a) : CUDART_INF_F;  // raw thresholds (temp)
        sw3[0][t] = W3[f * 256 + t];
        sw3[1][t] = W3[f * 256 + 64 + t];
        sw3[2][t] = W3[f * 256 + 128 + t];
        sw3[3][t] = W3[f * 256 + 192 + t];
    }
    if (t >= 64 && t < 68) sb3v[t - 64] = b3[f * 4 + (t - 64)];
    __syncthreads();

    // redundant per-block rank sort of the 64 layer-1 breakpoints
    if (t < 64) {
        float tk = sx[t];
        int r = 0;
        for (int j = 0; j < 64; ++j) {
            float tj = sx[j];
            r += (tj < tk) || (tj == tk && j < t);
        }
        srank[t] = r;
        sthr[r] = tk;
    }
    __syncthreads();

    // block s==0 of each flow publishes the header (sorted thr + wc + c)
    if (s == 0) {
        if (t < 64) g_hdr[f][t] = sthr[t];
        if (t == 64) {
            float el[3], shv[3];
            for (int d = 0; d < 3; d++) { el[d] = expf(ls[f * 3 + d]); shv[d] = sh[f * 3 + d]; }
            float l[3][3], U[3][3];
            for (int aa = 0; aa < 3; aa++)
                for (int bb = 0; bb < 3; bb++) {
                    l[aa][bb] = (bb < aa ? lm[f * 9 + aa * 3 + bb] : (aa == bb ? 1.f : 0.f));
                    U[aa][bb] = (bb > aa ? um[f * 9 + aa * 3 + bb] : 0.f);
                }
            for (int d = 0; d < 3; d++) U[d][d] = ss[f * 3 + d] * expf(lls[f * 3 + d]);
            float A[3][3], Wm[3][3];
            for (int aa = 0; aa < 3; aa++)
                for (int bb = 0; bb < 3; bb++) {
                    float s2 = 0.f;
                    for (int q = 0; q < 3; q++) s2 += l[aa][q] * U[q][bb];
                    A[aa][bb] = s2;
                }
            for (int aa = 0; aa < 3; aa++)
                for (int bb = 0; bb < 3; bb++) {
                    float s2 = 0.f;
                    for (int q = 0; q < 3; q++) s2 += P[f * 9 + aa * 3 + q] * A[q][bb];
                    Wm[aa][bb] = s2;
                }
            for (int aa = 0; aa < 3; aa++) {
                float cs = 0.f;
                for (int bb = 0; bb < 3; bb++) {
                    float wcv = Wm[aa][bb] * el[bb];
                    g_hdr[f][64 + aa * 3 + bb] = wcv;
                    cs += wcv * shv[bb];
                }
                g_hdr[f][73 + aa] = cs;
            }
        }
        if (f == 0 && t == 65) {
            float Lt[3][3], cov[3][3];
            for (int aa = 0; aa < 3; aa++)
                for (int bb = 0; bb < 3; bb++)
                    Lt[aa][bb] = (bb <= aa ? L_tril[aa * 3 + bb] : 0.f) + (aa == bb ? 1e-6f : 0.f);
            for (int aa = 0; aa < 3; aa++)
                for (int bb = 0; bb < 3; bb++) {
                    float s2 = 0.f;
                    for (int q = 0; q < 3; q++) s2 += Lt[aa][q] * Lt[bb][q];
                    cov[aa][bb] = s2;
                }
            float L00 = sqrtf(cov[0][0]);
            float L10 = cov[1][0] / L00, L20 = cov[2][0] / L00;
            float L11 = sqrtf(cov[1][1] - L10 * L10);
            float L21 = (cov[2][1] - L20 * L10) / L11;
            float L22 = sqrtf(cov[2][2] - L20 * L20 - L21 * L21);
            float Lm[9] = {L00, 0.f, 0.f, L10, L11, 0.f, L20, L21, L22};
            for (int q = 0; q < 9; q++) g_L[q] = Lm[q];
            for (int q = 0; q < 3; q++) g_bm[q] = bm[q];
        }
        if (f == 0 && t == 66) {
            float tot = 0.f;
            for (int q = 0; q < NFLOWS * 3; q++) tot += ls[q] + lls[q];
            g_totc = tot;
        }
    }

    const float lo = (s == 0)  ? -CUDART_INF_F : sthr[s - 1];
    const float hi = (s == 64) ?  CUDART_INF_F : sthr[s];

    if (t < 64) {
        const int u = t;
        float Pd = 0.f, Qd = b2[f * 64 + u];
        for (int j = 0; j < 64; ++j) {
            float aj = sa[j];
            bool act = (aj > 0.f) ? (srank[j] < s)
                     : (aj < 0.f) ? (srank[j] >= s)
                                  : (sbv[j] > 0.f);
            if (act) {
                float w = sW2[u * 64 + j];
                Pd = fmaf(w, aj, Pd);
                Qd = fmaf(w, sbv[j], Qd);
            }
        }
        sP[u] = Pd; sQ[u] = Qd;
        float xu = (Pd != 0.f) ? (-Qd / Pd) : CUDART_INF_F;
        bool inside = (Pd != 0.f) && (xu > lo) && (xu < hi);
        sx[u]  = inside ? xu : CUDART_INF_F;
        sin_[u] = inside ? 1 : 0;
        bool a0;                                // active just above lo?
        if (Pd > 0.f)      a0 = (xu <= lo);
        else if (Pd < 0.f) a0 = (xu > lo);
        else               a0 = (Qd > 0.f);
        sact0[u] = a0 ? 1 : 0;
    }
    __syncthreads();
    if (t < 64) {
        float key = sx[t];
        int r = 0;
        for (int j = 0; j < 64; ++j) {
            float xj = sx[j];
            r += (xj < key) || (xj == key && j < t);
        }
        ssub[t] = r;
        g_sub[f][s * 65 + r] = key;               // sorted (INF pads at top)
        if (t == 0) g_sub[f][s * 65 + 64] = CUDART_INF_F;
    }
    __syncthreads();
    if (t < 65) {                                 // sub-segment j = t
        float al0 = 0.f, al1 = 0.f, al2 = 0.f, al3 = 0.f;
        float be0 = sb3v[0], be1 = sb3v[1], be2 = sb3v[2], be3 = sb3v[3];
        for (int u = 0; u < 64; ++u) {
            bool act = (sact0[u] != 0) != ((sin_[u] != 0) && (ssub[u] < t));
            if (act) {
                float Pu = sP[u], Qu = sQ[u];
                float w0 = sw3[0][u], w1 = sw3[1][u], w2 = sw3[2][u], w3v = sw3[3][u];
                al0 = fmaf(w0, Pu, al0); al1 = fmaf(w1, Pu, al1);
                al2 = fmaf(w2, Pu, al2); al3 = fmaf(w3v, Pu, al3);
                be0 = fmaf(w0, Qu, be0); be1 = fmaf(w1, Qu, be1);
                be2 = fmaf(w2, Qu, be2); be3 = fmaf(w3v, Qu, be3);
            }
        }
        int idx = s * 65 + t;
        // pack 8 fp16 into one 16B entry: {al0..3, be0..3}
        __half2 p0 = __floats2half2_rn(al0, al1);
        __half2 p1 = __floats2half2_rn(al2, al3);
        __half2 p2 = __floats2half2_rn(be0, be1);
        __half2 p3 = __floats2half2_rn(be2, be3);
        uint4 pk;
        pk.x = *(unsigned int*)&p0;
        pk.y = *(unsigned int*)&p1;
        pk.z = *(unsigned int*)&p2;
        pk.w = *(unsigned int*)&p3;
        *((uint4*)g_coefh[f] + idx) = pk;
    }
}

// ---------------------------------------------------------------------------
// Main kernel (R9 structure — best measured total): 256 threads/CTA,
// 4 samples/thread, smem-staged fp32 tables, two 6-step smem searches,
// ONE 16B fp16 coef gather (was two 16B fp32 — the dominant wavefront term).
// ---------------------------------------------------------------------------
__global__ __launch_bounds__(256)
void glow_main(const float* __restrict__ eps, float* __restrict__ out, int N) {
    __shared__ float sm[80 + 4228];

    const int tid = threadIdx.x;
    int   idx[4];
    bool  vld[4];
    float z0[4], z1[4], z2[4], ldv[4];

    const float L0 = g_L[0], L3 = g_L[3], L4 = g_L[4],
                L6 = g_L[6], L7 = g_L[7], L8 = g_L[8];
    const float m0 = g_bm[0], m1 = g_bm[1], m2 = g_bm[2];

    #pragma unroll
    for (int q = 0; q < 4; ++q) {
        int gi = blockIdx.x * 1024 + q * 256 + tid;
        vld[q] = gi < N;
        int i = vld[q] ? gi : (N - 1);
        idx[q] = i;
        float e0 = eps[3 * i], e1 = eps[3 * i + 1], e2 = eps[3 * i + 2];
        z0[q] = m0 + L0 * e0;
        z1[q] = m1 + L3 * e0 + L4 * e1;
        z2[q] = m2 + L6 * e0 + L7 * e1 + L8 * e2;
        ldv[q] = 0.f;
    }

    for (int f = 0; f < NFLOWS; ++f) {
        __syncthreads();                       // protect smem from prior flow readers
        if (tid < 20) ((float4*)sm)[tid] = ((const float4*)g_hdr[f])[tid];
        {
            float4* ds = (float4*)(sm + 80);
            const float4* s4 = (const float4*)g_sub[f];
            #pragma unroll
            for (int q = 0; q < 4; ++q) ds[tid + q * 256] = s4[tid + q * 256];
            if (tid < 33) ds[tid + 1024] = s4[tid + 1024];
        }
        __syncthreads();

        // folded actnorm + 1x1 conv
        const float* wcp = sm + 64;
        const float w0 = wcp[0], w1 = wcp[1], w2 = wcp[2];
        const float w3v = wcp[3], w4 = wcp[4], w5 = wcp[5];
        const float w6 = wcp[6], w7 = wcp[7], w8 = wcp[8];
        const float c0 = wcp[9], c1 = wcp[10], c2 = wcp[11];
        #pragma unroll
        for (int q = 0; q < 4; ++q) {
            float n0 = c0 + w0 * z0[q] + w1 * z1[q] + w2 * z2[q];
            float n1 = c1 + w3v * z0[q] + w4 * z1[q] + w5 * z2[q];
            float n2 = c2 + w6 * z0[q] + w7 * z1[q] + w8 * z2[q];
            z0[q] = n0; z1[q] = n1; z2[q] = n2;
        }

        // coarse segment rank in [0,64] — 4 independent chains
        const float* thr = sm;
        int sS[4];
        #pragma unroll
        for (int q = 0; q < 4; ++q) sS[q] = 0;
        #pragma unroll
        for (int st = 32; st; st >>= 1) {
            #pragma unroll
            for (int q = 0; q < 4; ++q)
                if (thr[sS[q] + st - 1] < z0[q]) sS[q] += st;
        }
        #pragma unroll
        for (int q = 0; q < 4; ++q)
            if (sS[q] == 63 && thr[63] < z0[q]) sS[q] = 64;

        // fine sub-segment rank in [0,64]
        int jS[4];
        #pragma unroll
        for (int q = 0; q < 4; ++q) jS[q] = 0;
        #pragma unroll
        for (int st = 32; st; st >>= 1) {
            #pragma unroll
            for (int q = 0; q < 4; ++q) {
                const float* sub = sm + 80 + sS[q] * 65;
                if (sub[jS[q] + st - 1] < z0[q]) jS[q] += st;
            }
        }
        #pragma unroll
        for (int q = 0; q < 4; ++q) {
            const float* sub = sm + 80 + sS[q] * 65;
            if (jS[q] == 63 && sub[63] < z0[q]) jS[q] = 64;
        }

        // exact affine MLP output: ONE 16B fp16 coef gather per sample
        uint4 ce[4];
        #pragma unroll
        for (int q = 0; q < 4; ++q)
            ce[q] = __ldg((const uint4*)g_coefh[f] + (sS[q] * 65 + jS[q]));
        #pragma unroll
        for (int q = 0; q < 4; ++q) {
            float2 a01 = __half22float2(*(__half2*)&ce[q].x);
            float2 a23 = __half22float2(*(__half2*)&ce[q].y);
            float2 b01 = __half22float2(*(__half2*)&ce[q].z);
            float2 b23 = __half22float2(*(__half2*)&ce[q].w);
            float x = z0[q];
            float o0 = fmaf(a01.x, x, b01.x), o1 = fmaf(a01.y, x, b01.y);
            float o2 = fmaf(a23.x, x, b23.x), o3 = fmaf(a23.y, x, b23.y);
            z1[q] = fmaf(z1[q], __expf(o2), o0);
            z2[q] = fmaf(z2[q], __expf(o3), o1);
            ldv[q] += o2 + o3;
        }
    }

    const float totc = g_totc;
    #pragma unroll
    for (int q = 0; q < 4; ++q) {
        if (vld[q]) {
            int i = idx[q];
            out[3 * i]     = z0[q];
            out[3 * i + 1] = __expf(z1[q]);
            out[3 * i + 2] = __expf(z2[q]);
            out[3 * N + i] = ldv[q] + totc + z1[q] + z2[q];
        }
    }
}

// ---------------------------------------------------------------------------
// Launch. Inputs (metadata order): eps, L_tril, base_mean, an_log_scale,
// an_shift, perm_p, sign_s, lu_l, lu_u, lu_log_s, W1, b1, W2, b2, W3, b3
// Output: [z_t (N,3) row-major][log_det (N)] float32 (layout verified R4..R14)
// ---------------------------------------------------------------------------
extern "C" void kernel_launch(void* const* d_in, const int* in_sizes, int n_in,
                              void* d_out, int out_size) {
    const float* eps    = (const float*)d_in[0];
    const float* L_tril = (const float*)d_in[1];
    const float* bm     = (const float*)d_in[2];
    const float* an_ls  = (const float*)d_in[3];
    const float* an_sh  = (const float*)d_in[4];
    const float* perm   = (const float*)d_in[5];
    const float* ss     = (const float*)d_in[6];
    const float* lu_l   = (const float*)d_in[7];
    const float* lu_u   = (const float*)d_in[8];
    const float* lu_ls  = (const float*)d_in[9];
    const float* W1     = (const float*)d_in[10];
    const float* b1     = (const float*)d_in[11];
    const float* W2     = (const float*)d_in[12];
    const float* b2     = (const float*)d_in[13];
    const float* W3     = (const float*)d_in[14];
    const float* b3     = (const float*)d_in[15];
    float* out = (float*)d_out;

    int N = in_sizes[0] / 3;

    k_prep<<<dim3(65, NFLOWS), 128>>>(L_tril, bm, an_ls, an_sh, perm, ss,
                                      lu_l, lu_u, lu_ls, W1, b1, W2, b2, W3, b3);
    glow_main<<<(N + 1023) / 1024, 256>>>(eps, out, N);
}